// round 5
// baseline (speedup 1.0000x reference)
#include <cuda_runtime.h>
#include <math.h>
#include <stdint.h>

// Problem constants (fixed by the reference)
#define Bsz   4096
#define INDIM 1024
#define Dm    512
#define Nn    8
#define Ss    128
#define HOPS  4
#define MAXT  72      // max token tiles per hop: 4096/64 + 8

// -------- device scratch (no allocations allowed) --------
__device__ float g_z[Bsz * Dm];        // ping buffer (also holds z)
__device__ float g_buf[Bsz * Dm];      // pong buffer
__device__ float g_symmean[Bsz * Ss];
__device__ int   g_prog[Bsz * HOPS];
__device__ int   g_order[HOPS][Bsz];
__device__ int   g_tileE[HOPS][MAXT];
__device__ int   g_tileS[HOPS][MAXT];
__device__ int   g_tileC[HOPS][MAXT];
__device__ int   g_numTiles[HOPS];
// pre-split tf32 hi/lo weights
__device__ uint32_t g_WinH[INDIM * Dm],  g_WinL[INDIM * Dm];
__device__ uint32_t g_symWH[Nn * Dm * Ss], g_symWL[Nn * Dm * Ss];
__device__ uint32_t g_opsWH[Nn * Dm * Dm], g_opsWL[Nn * Dm * Dm];

__device__ __forceinline__ float gelu_tanh(float x) {
    float x3 = x * x * x;
    return 0.5f * x * (1.0f + tanhf(0.7978845608028654f * (x + 0.044715f * x3)));
}

// ---------------- 3xTF32 helpers ----------------
__device__ __forceinline__ uint32_t f2tf(float v) {
    uint32_t r; asm("cvt.rna.tf32.f32 %0, %1;" : "=r"(r) : "f"(v)); return r;
}
__device__ __forceinline__ void split4(float4 v, uint4& h, uint4& l) {
    h.x = f2tf(v.x); h.y = f2tf(v.y); h.z = f2tf(v.z); h.w = f2tf(v.w);
    l.x = f2tf(__fsub_rn(v.x, __uint_as_float(h.x)));
    l.y = f2tf(__fsub_rn(v.y, __uint_as_float(h.y)));
    l.z = f2tf(__fsub_rn(v.z, __uint_as_float(h.z)));
    l.w = f2tf(__fsub_rn(v.w, __uint_as_float(h.w)));
}

#define MMA(d, a, b)                                                          \
    asm("mma.sync.aligned.m16n8k8.row.col.f32.tf32.tf32.f32 "                 \
        "{%0,%1,%2,%3}, {%4,%5,%6,%7}, {%8,%9}, {%0,%1,%2,%3};"               \
        : "+f"(d[0]), "+f"(d[1]), "+f"(d[2]), "+f"(d[3])                      \
        : "r"(a[0]), "r"(a[1]), "r"(a[2]), "r"(a[3]), "r"(b[0]), "r"(b[1]))

// One k8 step: warp (wm,wn) computes its 32x32 with 3xTF32 (2 m-tiles x 4 n-tiles).
__device__ __forceinline__ void mma_k8(
    const uint32_t Ah[64][36], const uint32_t Al[64][36],
    const uint32_t Bh[32][68], const uint32_t Bl[32][68],
    int wm, int wn, int lane, int k8, float acc[2][4][4]) {
    const int lr = lane >> 2, lc = lane & 3;
    uint32_t ah[2][4], al[2][4];
#pragma unroll
    for (int mt = 0; mt < 2; mt++) {
        int m = wm * 32 + mt * 16 + lr;
        ah[mt][0] = Ah[m][k8 + lc];       ah[mt][1] = Ah[m + 8][k8 + lc];
        ah[mt][2] = Ah[m][k8 + lc + 4];   ah[mt][3] = Ah[m + 8][k8 + lc + 4];
        al[mt][0] = Al[m][k8 + lc];       al[mt][1] = Al[m + 8][k8 + lc];
        al[mt][2] = Al[m][k8 + lc + 4];   al[mt][3] = Al[m + 8][k8 + lc + 4];
    }
#pragma unroll
    for (int nt = 0; nt < 4; nt++) {
        int n = wn * 32 + nt * 8 + lr;
        uint32_t bh[2], bl[2];
        bh[0] = Bh[k8 + lc][n]; bh[1] = Bh[k8 + lc + 4][n];
        bl[0] = Bl[k8 + lc][n]; bl[1] = Bl[k8 + lc + 4][n];
#pragma unroll
        for (int mt = 0; mt < 2; mt++) {
            MMA(acc[mt][nt], ah[mt], bl);
            MMA(acc[mt][nt], al[mt], bh);
            MMA(acc[mt][nt], ah[mt], bh);
        }
    }
}

// ============ weight pre-split (once per launch; bit-identical to in-kernel split) ====
__global__ void split_sel(const float* __restrict__ src, int sel, int n4) {
    int i = blockIdx.x * blockDim.x + threadIdx.x;
    if (i >= n4) return;
    uint32_t* hi = (sel == 0) ? g_WinH : (sel == 1) ? g_symWH : g_opsWH;
    uint32_t* lo = (sel == 0) ? g_WinL : (sel == 1) ? g_symWL : g_opsWL;
    float4 v = reinterpret_cast<const float4*>(src)[i];
    uint4 h, l; split4(v, h, l);
    reinterpret_cast<uint4*>(hi)[i] = h;
    reinterpret_cast<uint4*>(lo)[i] = l;
}

// ============ GEMM 1 (3xTF32, prefetch): z = x @ W_in + b_in ============
__global__ __launch_bounds__(128) void gemm_z_tc(
    const float* __restrict__ A, const float* __restrict__ bias) {
    __shared__ uint32_t Ah[64][36], Al[64][36], Bh[32][68], Bl[32][68];
    const int tid = threadIdx.x, lane = tid & 31, warp = tid >> 5;
    const int wm = warp & 1, wn = warp >> 1;
    const int bm = blockIdx.x * 64, bn = blockIdx.y * 64;
    const int mrow = tid >> 3, kq = (tid & 7) * 4;
    const int brow = tid >> 4, nq = (tid & 15) * 4;
    float acc[2][4][4] = {};
    float4 aReg[4]; uint4 bhReg[4], blReg[4];
#pragma unroll
    for (int i = 0; i < 4; i++) {
        aReg[i]  = *reinterpret_cast<const float4*>(A + (size_t)(bm + i * 16 + mrow) * INDIM + kq);
        bhReg[i] = *reinterpret_cast<const uint4*>(g_WinH + (size_t)(i * 8 + brow) * Dm + bn + nq);
        blReg[i] = *reinterpret_cast<const uint4*>(g_WinL + (size_t)(i * 8 + brow) * Dm + bn + nq);
    }
    for (int k0 = 0; k0 < INDIM; k0 += 32) {
#pragma unroll
        for (int i = 0; i < 4; i++) {
            uint4 h, l; split4(aReg[i], h, l);
            *reinterpret_cast<uint4*>(&Ah[i * 16 + mrow][kq]) = h;
            *reinterpret_cast<uint4*>(&Al[i * 16 + mrow][kq]) = l;
            *reinterpret_cast<uint4*>(&Bh[i * 8 + brow][nq]) = bhReg[i];
            *reinterpret_cast<uint4*>(&Bl[i * 8 + brow][nq]) = blReg[i];
        }
        __syncthreads();
        if (k0 + 32 < INDIM) {
#pragma unroll
            for (int i = 0; i < 4; i++) {
                aReg[i]  = *reinterpret_cast<const float4*>(A + (size_t)(bm + i * 16 + mrow) * INDIM + k0 + 32 + kq);
                bhReg[i] = *reinterpret_cast<const uint4*>(g_WinH + (size_t)(k0 + 32 + i * 8 + brow) * Dm + bn + nq);
                blReg[i] = *reinterpret_cast<const uint4*>(g_WinL + (size_t)(k0 + 32 + i * 8 + brow) * Dm + bn + nq);
            }
        }
        mma_k8(Ah, Al, Bh, Bl, wm, wn, lane, 0, acc);
        mma_k8(Ah, Al, Bh, Bl, wm, wn, lane, 8, acc);
        mma_k8(Ah, Al, Bh, Bl, wm, wn, lane, 16, acc);
        mma_k8(Ah, Al, Bh, Bl, wm, wn, lane, 24, acc);
        __syncthreads();
    }
    const int lr = lane >> 2, lc = lane & 3;
#pragma unroll
    for (int mt = 0; mt < 2; mt++)
#pragma unroll
        for (int nt = 0; nt < 4; nt++) {
            int m0 = bm + wm * 32 + mt * 16 + lr;
            int n0 = bn + wn * 32 + nt * 8 + 2 * lc;
            float b0 = bias[n0], b1 = bias[n0 + 1];
            g_z[(size_t)m0 * Dm + n0]           = acc[mt][nt][0] + b0;
            g_z[(size_t)m0 * Dm + n0 + 1]       = acc[mt][nt][1] + b1;
            g_z[(size_t)(m0 + 8) * Dm + n0]     = acc[mt][nt][2] + b0;
            g_z[(size_t)(m0 + 8) * Dm + n0 + 1] = acc[mt][nt][3] + b1;
        }
}

// ======= GEMM 2 (3xTF32, prefetch): sym[b, n*128+s] = sum_d z[b,d]*sym_W[n,d,s] =======
__global__ __launch_bounds__(128) void gemm_sym_tc(float* __restrict__ symOut) {
    __shared__ uint32_t Ah[64][36], Al[64][36], Bh[32][68], Bl[32][68];
    const int tid = threadIdx.x, lane = tid & 31, warp = tid >> 5;
    const int wm = warp & 1, wn = warp >> 1;
    const int bm = blockIdx.x * 64, bn = blockIdx.y * 64;
    const int mrow = tid >> 3, kq = (tid & 7) * 4;
    const int brow = tid >> 4, nq = (tid & 15) * 4;
    const size_t boff = (size_t)(bn >> 7) * (Dm * Ss) + (bn & 127);
    float acc[2][4][4] = {};
    float4 aReg[4]; uint4 bhReg[4], blReg[4];
#pragma unroll
    for (int i = 0; i < 4; i++) {
        aReg[i]  = *reinterpret_cast<const float4*>(g_z + (size_t)(bm + i * 16 + mrow) * Dm + kq);
        bhReg[i] = *reinterpret_cast<const uint4*>(g_symWH + boff + (size_t)(i * 8 + brow) * Ss + nq);
        blReg[i] = *reinterpret_cast<const uint4*>(g_symWL + boff + (size_t)(i * 8 + brow) * Ss + nq);
    }
    for (int k0 = 0; k0 < Dm; k0 += 32) {
#pragma unroll
        for (int i = 0; i < 4; i++) {
            uint4 h, l; split4(aReg[i], h, l);
            *reinterpret_cast<uint4*>(&Ah[i * 16 + mrow][kq]) = h;
            *reinterpret_cast<uint4*>(&Al[i * 16 + mrow][kq]) = l;
            *reinterpret_cast<uint4*>(&Bh[i * 8 + brow][nq]) = bhReg[i];
            *reinterpret_cast<uint4*>(&Bl[i * 8 + brow][nq]) = blReg[i];
        }
        __syncthreads();
        if (k0 + 32 < Dm) {
#pragma unroll
            for (int i = 0; i < 4; i++) {
                aReg[i]  = *reinterpret_cast<const float4*>(g_z + (size_t)(bm + i * 16 + mrow) * Dm + k0 + 32 + kq);
                bhReg[i] = *reinterpret_cast<const uint4*>(g_symWH + boff + (size_t)(k0 + 32 + i * 8 + brow) * Ss + nq);
                blReg[i] = *reinterpret_cast<const uint4*>(g_symWL + boff + (size_t)(k0 + 32 + i * 8 + brow) * Ss + nq);
            }
        }
        mma_k8(Ah, Al, Bh, Bl, wm, wn, lane, 0, acc);
        mma_k8(Ah, Al, Bh, Bl, wm, wn, lane, 8, acc);
        mma_k8(Ah, Al, Bh, Bl, wm, wn, lane, 16, acc);
        mma_k8(Ah, Al, Bh, Bl, wm, wn, lane, 24, acc);
        __syncthreads();
    }
    const int lr = lane >> 2, lc = lane & 3;
#pragma unroll
    for (int mt = 0; mt < 2; mt++)
#pragma unroll
        for (int nt = 0; nt < 4; nt++) {
            int m0 = bm + wm * 32 + mt * 16 + lr;
            int n0 = bn + wn * 32 + nt * 8 + 2 * lc;
            symOut[(size_t)m0 * (Nn * Ss) + n0]           = acc[mt][nt][0];
            symOut[(size_t)m0 * (Nn * Ss) + n0 + 1]       = acc[mt][nt][1];
            symOut[(size_t)(m0 + 8) * (Nn * Ss) + n0]     = acc[mt][nt][2];
            symOut[(size_t)(m0 + 8) * (Nn * Ss) + n0 + 1] = acc[mt][nt][3];
        }
}

// ================== symmean[b,s] = mean_n sym[b,n,s] ==================
__global__ void mean_kernel(const float* __restrict__ symOut) {
    int i = blockIdx.x * blockDim.x + threadIdx.x;
    int b = i >> 7, s = i & 127;
    const float* p = symOut + (size_t)b * (Nn * Ss) + s;
    float sum = 0.f;
#pragma unroll
    for (int n = 0; n < Nn; n++) sum += p[n * Ss];
    g_symmean[i] = sum * 0.125f;
}

// ====== router: compensated-fp32 logits + argmax -> prog (frozen since R3) ======
__global__ __launch_bounds__(288) void router_kernel(
    const float* __restrict__ RW, const float* __restrict__ rb, float* __restrict__ progf) {
    __shared__ float rin[8][644];
    __shared__ float lg[8][36];
    const int b0 = blockIdx.x * 8;
    const int tid = threadIdx.x;
    for (int i = tid; i < 8 * 640; i += 288) {
        int t = i / 640, k = i - t * 640;
        rin[t][k] = (k < Dm) ? g_z[(size_t)(b0 + t) * Dm + k]
                             : g_symmean[(size_t)(b0 + t) * Ss + (k - Dm)];
    }
    __syncthreads();
    {
        const int t = tid / 36, j = tid - t * 36;
        const float* rw = RW + j;
        float s[4] = {0.f, 0.f, 0.f, 0.f};
        float c[4] = {0.f, 0.f, 0.f, 0.f};
#pragma unroll 2
        for (int k = 0; k < 640; k += 4) {
#pragma unroll
            for (int i = 0; i < 4; i++) {
                float x = rin[t][k + i];
                float w = __ldg(&rw[(k + i) * 36]);
                float p = __fmul_rn(x, w);
                float e = __fmaf_rn(x, w, -p);
                float t1  = __fadd_rn(s[i], p);
                float bb  = __fsub_rn(t1, s[i]);
                float er1 = __fadd_rn(__fsub_rn(s[i], __fsub_rn(t1, bb)),
                                      __fsub_rn(p, bb));
                s[i] = t1;
                c[i] = __fadd_rn(c[i], __fadd_rn(er1, e));
            }
        }
        float S = rb[j], C = 0.f;
#pragma unroll
        for (int i = 0; i < 4; i++) {
            float t1  = __fadd_rn(S, s[i]);
            float bb  = __fsub_rn(t1, S);
            float er1 = __fadd_rn(__fsub_rn(S, __fsub_rn(t1, bb)),
                                  __fsub_rn(s[i], bb));
            S = t1;
            C = __fadd_rn(C, __fadd_rn(er1, c[i]));
        }
        lg[t][j] = __fadd_rn(S, C);
    }
    __syncthreads();
    if (tid < 32) {
        int t = tid >> 2, h = tid & 3;
        const float* l = &lg[t][h * 9];
        float best = l[0]; int bi = 0;
#pragma unroll
        for (int j = 1; j < 9; j++)
            if (l[j] > best) { best = l[j]; bi = j; }
        g_prog[(b0 + t) * HOPS + h] = bi;
        progf[(b0 + t) * HOPS + h] = (float)bi;
    }
}

// ======= schedule: group active tokens by (hop, expert); build 64-row tiles =======
__global__ void schedule_kernel() {
    __shared__ int cnt[HOPS][Nn];
    __shared__ int cur[HOPS][Nn];
    const int tid = threadIdx.x;
    if (tid < HOPS * Nn) cnt[tid / Nn][tid % Nn] = 0;
    __syncthreads();
    for (int b = tid; b < Bsz; b += blockDim.x) {
        bool act = true;
        for (int t = 0; t < HOPS; t++) {
            int e = g_prog[b * HOPS + t];
            act = act && (e != Nn);
            if (act) atomicAdd(&cnt[t][e], 1);
        }
    }
    __syncthreads();
    if (tid < HOPS) {
        int t = tid, p = 0, nt = 0;
        for (int e = 0; e < Nn; e++) {
            cur[t][e] = p;
            int c = cnt[t][e], q = p;
            while (c > 0) {
                g_tileE[t][nt] = e; g_tileS[t][nt] = q;
                g_tileC[t][nt] = (c < 64) ? c : 64;
                q += 64; c -= 64; nt++;
            }
            p += cnt[t][e];
        }
        g_numTiles[t] = nt;
    }
    __syncthreads();
    for (int b = tid; b < Bsz; b += blockDim.x) {
        bool act = true;
        for (int t = 0; t < HOPS; t++) {
            int e = g_prog[b * HOPS + t];
            act = act && (e != Nn);
            if (act) { int p = atomicAdd(&cur[t][e], 1); g_order[t][p] = b; }
        }
    }
}

// == hop (3xTF32, prefetch): dst[tok] = gelu(src[tok] @ ops_W[e] + ops_b[e]) ==
// No inter-hop copies: active(h+1) ⊆ active(h), so hop h+1 only reads rows hop h wrote.
__global__ __launch_bounds__(128) void hop_tc(
    int hop, int srcSel, const float* __restrict__ opsB) {
    if ((int)blockIdx.x >= g_numTiles[hop]) return;
    const float* src = (srcSel == 0) ? g_z : g_buf;
    float* dst = (srcSel == 0) ? g_buf : g_z;
    const int e     = g_tileE[hop][blockIdx.x];
    const int start = g_tileS[hop][blockIdx.x];
    const int cnt   = g_tileC[hop][blockIdx.x];
    const int bn    = blockIdx.y * 64;
    __shared__ int toks[64];
    __shared__ uint32_t Ah[64][36], Al[64][36], Bh[32][68], Bl[32][68];
    const int tid = threadIdx.x, lane = tid & 31, warp = tid >> 5;
    const int wm = warp & 1, wn = warp >> 1;
    const int mrow = tid >> 3, kq = (tid & 7) * 4;
    const int brow = tid >> 4, nq = (tid & 15) * 4;
    if (tid < 64) toks[tid] = (tid < cnt) ? g_order[hop][start + tid] : -1;
    __syncthreads();
    int myTok[4];
#pragma unroll
    for (int i = 0; i < 4; i++) myTok[i] = toks[i * 16 + mrow];
    const uint32_t* WH = g_opsWH + (size_t)e * (Dm * Dm);
    const uint32_t* WL = g_opsWL + (size_t)e * (Dm * Dm);
    float acc[2][4][4] = {};
    float4 aReg[4]; uint4 bhReg[4], blReg[4];
#pragma unroll
    for (int i = 0; i < 4; i++) {
        aReg[i] = make_float4(0.f, 0.f, 0.f, 0.f);
        if (myTok[i] >= 0)
            aReg[i] = *reinterpret_cast<const float4*>(src + (size_t)myTok[i] * Dm + kq);
        bhReg[i] = *reinterpret_cast<const uint4*>(WH + (size_t)(i * 8 + brow) * Dm + bn + nq);
        blReg[i] = *reinterpret_cast<const uint4*>(WL + (size_t)(i * 8 + brow) * Dm + bn + nq);
    }
    for (int k0 = 0; k0 < Dm; k0 += 32) {
#pragma unroll
        for (int i = 0; i < 4; i++) {
            uint4 h, l; split4(aReg[i], h, l);
            *reinterpret_cast<uint4*>(&Ah[i * 16 + mrow][kq]) = h;
            *reinterpret_cast<uint4*>(&Al[i * 16 + mrow][kq]) = l;
            *reinterpret_cast<uint4*>(&Bh[i * 8 + brow][nq]) = bhReg[i];
            *reinterpret_cast<uint4*>(&Bl[i * 8 + brow][nq]) = blReg[i];
        }
        __syncthreads();
        if (k0 + 32 < Dm) {
#pragma unroll
            for (int i = 0; i < 4; i++) {
                if (myTok[i] >= 0)
                    aReg[i] = *reinterpret_cast<const float4*>(src + (size_t)myTok[i] * Dm + k0 + 32 + kq);
                bhReg[i] = *reinterpret_cast<const uint4*>(WH + (size_t)(k0 + 32 + i * 8 + brow) * Dm + bn + nq);
                blReg[i] = *reinterpret_cast<const uint4*>(WL + (size_t)(k0 + 32 + i * 8 + brow) * Dm + bn + nq);
            }
        }
        mma_k8(Ah, Al, Bh, Bl, wm, wn, lane, 0, acc);
        mma_k8(Ah, Al, Bh, Bl, wm, wn, lane, 8, acc);
        mma_k8(Ah, Al, Bh, Bl, wm, wn, lane, 16, acc);
        mma_k8(Ah, Al, Bh, Bl, wm, wn, lane, 24, acc);
        __syncthreads();
    }
    const int lr = lane >> 2, lc = lane & 3;
#pragma unroll
    for (int mt = 0; mt < 2; mt++) {
        int r0 = wm * 32 + mt * 16 + lr;
        int tk0 = toks[r0], tk1 = toks[r0 + 8];
#pragma unroll
        for (int nt = 0; nt < 4; nt++) {
            int n0 = bn + wn * 32 + nt * 8 + 2 * lc;
            float b0 = opsB[e * Dm + n0], b1 = opsB[e * Dm + n0 + 1];
            if (tk0 >= 0) {
                dst[(size_t)tk0 * Dm + n0]     = gelu_tanh(acc[mt][nt][0] + b0);
                dst[(size_t)tk0 * Dm + n0 + 1] = gelu_tanh(acc[mt][nt][1] + b1);
            }
            if (tk1 >= 0) {
                dst[(size_t)tk1 * Dm + n0]     = gelu_tanh(acc[mt][nt][2] + b0);
                dst[(size_t)tk1 * Dm + n0 + 1] = gelu_tanh(acc[mt][nt][3] + b1);
            }
        }
    }
}

// ===== final gather: out[b] = buffer holding b's value after its last active hop =====
// value after hop k lives in: hop0->g_buf, hop1->g_z, hop2->g_buf, hop3->g_z
// nact = #active hops (prefix). nact odd -> g_buf, even (incl 0) -> g_z.
__global__ void gather_out(float* __restrict__ out) {
    int idx = blockIdx.x * blockDim.x + threadIdx.x;   // over Bsz*Dm/4 float4s
    int b = idx >> 7;
    int nact = 0;
#pragma unroll
    for (int t = 0; t < HOPS; t++) {
        if (g_prog[b * HOPS + t] == Nn) break;
        nact++;
    }
    const float* src = (nact & 1) ? g_buf : g_z;
    reinterpret_cast<float4*>(out)[idx] = reinterpret_cast<const float4*>(src)[idx];
}

// =========================== launch ===========================
extern "C" void kernel_launch(void* const* d_in, const int* in_sizes, int n_in,
                              void* d_out, int out_size) {
    const float* x        = (const float*)d_in[0];
    const float* W_in     = (const float*)d_in[1];
    const float* b_in     = (const float*)d_in[2];
    const float* ops_W    = (const float*)d_in[3];
    const float* ops_b    = (const float*)d_in[4];
    const float* sym_W    = (const float*)d_in[5];
    const float* router_W = (const float*)d_in[6];
    const float* router_b = (const float*)d_in[7];
    (void)in_sizes; (void)n_in; (void)out_size;

    float* out   = (float*)d_out;                 // [B, D]
    float* progf = out + Bsz * Dm;                // [B, HOPS] as float
    float* sym   = progf + Bsz * HOPS;            // [B, N, S]

    // pre-split weights into tf32 hi/lo
    split_sel<<<(INDIM * Dm / 4 + 255) / 256, 256>>>(W_in, 0, INDIM * Dm / 4);
    split_sel<<<(Nn * Dm * Ss / 4 + 255) / 256, 256>>>(sym_W, 1, Nn * Dm * Ss / 4);
    split_sel<<<(Nn * Dm * Dm / 4 + 255) / 256, 256>>>(ops_W, 2, Nn * Dm * Dm / 4);

    gemm_z_tc   <<<dim3(Bsz / 64, Dm / 64), 128>>>(x, b_in);
    gemm_sym_tc <<<dim3(Bsz / 64, (Nn * Ss) / 64), 128>>>(sym);
    mean_kernel <<<(Bsz * Ss) / 256, 256>>>(sym);
    router_kernel<<<Bsz / 8, 288>>>(router_W, router_b, progf);
    schedule_kernel<<<1, 512>>>();

    hop_tc<<<dim3(MAXT, Dm / 64), 128>>>(0, 0, ops_b);  // z   -> buf
    hop_tc<<<dim3(MAXT, Dm / 64), 128>>>(1, 1, ops_b);  // buf -> z
    hop_tc<<<dim3(MAXT, Dm / 64), 128>>>(2, 0, ops_b);  // z   -> buf
    hop_tc<<<dim3(MAXT, Dm / 64), 128>>>(3, 1, ops_b);  // buf -> z

    gather_out<<<(Bsz * Dm / 4) / 256, 256>>>(out);
}

// round 6
// speedup vs baseline: 1.1203x; 1.1203x over previous
#include <cuda_runtime.h>
#include <math.h>
#include <stdint.h>

// Problem constants (fixed by the reference)
#define Bsz   4096
#define INDIM 1024
#define Dm    512
#define Nn    8
#define Ss    128
#define HOPS  4
#define MAXT  72      // max token tiles per hop: 4096/64 + 8

#define A_STRIDE 36   // words; fragment banks (4*lr+lc) conflict-free
#define B_STRIDE 72   // words; 72 mod 32 == 8 -> fragment banks (8*lc+lr) conflict-free
// dynamic smem layout (in words):
//   Ah [64][36] @ 0          (2304 words)
//   Al [64][36] @ 2304       (2304 words)
//   stage s (0/1): Bh [32][72] @ 4608 + s*4608, Bl @ +2304
#define SMEM_WORDS (4608 + 2 * 4608)
#define SMEM_BYTES (SMEM_WORDS * 4)   // 55296

// -------- device scratch (no allocations allowed) --------
__device__ float g_z[Bsz * Dm];        // ping buffer (also holds z)
__device__ float g_buf[Bsz * Dm];      // pong buffer
__device__ float g_symmean[Bsz * Ss];
__device__ int   g_prog[Bsz * HOPS];
__device__ int   g_order[HOPS][Bsz];
__device__ int   g_tileE[HOPS][MAXT];
__device__ int   g_tileS[HOPS][MAXT];
__device__ int   g_tileC[HOPS][MAXT];
__device__ int   g_numTiles[HOPS];
// pre-split tf32 hi/lo weights
__device__ uint32_t g_WinH[INDIM * Dm],  g_WinL[INDIM * Dm];
__device__ uint32_t g_symWH[Nn * Dm * Ss], g_symWL[Nn * Dm * Ss];
__device__ uint32_t g_opsWH[Nn * Dm * Dm], g_opsWL[Nn * Dm * Dm];

__device__ __forceinline__ float gelu_tanh(float x) {
    float x3 = x * x * x;
    return 0.5f * x * (1.0f + tanhf(0.7978845608028654f * (x + 0.044715f * x3)));
}

// ---------------- 3xTF32 helpers ----------------
__device__ __forceinline__ uint32_t f2tf(float v) {
    uint32_t r; asm("cvt.rna.tf32.f32 %0, %1;" : "=r"(r) : "f"(v)); return r;
}
__device__ __forceinline__ void split4(float4 v, uint4& h, uint4& l) {
    h.x = f2tf(v.x); h.y = f2tf(v.y); h.z = f2tf(v.z); h.w = f2tf(v.w);
    l.x = f2tf(__fsub_rn(v.x, __uint_as_float(h.x)));
    l.y = f2tf(__fsub_rn(v.y, __uint_as_float(h.y)));
    l.z = f2tf(__fsub_rn(v.z, __uint_as_float(h.z)));
    l.w = f2tf(__fsub_rn(v.w, __uint_as_float(h.w)));
}

#define MMA(d, a, b)                                                          \
    asm("mma.sync.aligned.m16n8k8.row.col.f32.tf32.tf32.f32 "                 \
        "{%0,%1,%2,%3}, {%4,%5,%6,%7}, {%8,%9}, {%0,%1,%2,%3};"               \
        : "+f"(d[0]), "+f"(d[1]), "+f"(d[2]), "+f"(d[3])                      \
        : "r"(a[0]), "r"(a[1]), "r"(a[2]), "r"(a[3]), "r"(b[0]), "r"(b[1]))

// ---------------- cp.async helpers ----------------
__device__ __forceinline__ void cp_async16(uint32_t saddr, const void* g) {
    asm volatile("cp.async.cg.shared.global [%0], [%1], 16;" :: "r"(saddr), "l"(g));
}
#define CP_COMMIT() asm volatile("cp.async.commit_group;")
#define CP_WAIT0()  asm volatile("cp.async.wait_group 0;" ::: "memory")

// Stage one 32x64 B slab (hi+lo) into stage s via cp.async. gbase = element offset
// of tile row 0 (k0 row) col 0 (bn) in the pre-split weight array; ldB = row stride.
__device__ __forceinline__ void stage_B(int s, const uint32_t* __restrict__ GH,
                                        const uint32_t* __restrict__ GL,
                                        size_t gbase, int ldB, int tid) {
    extern __shared__ uint32_t smem[];
    uint32_t base_h = (uint32_t)__cvta_generic_to_shared(smem + 4608 + s * 4608);
    uint32_t base_l = base_h + 2304 * 4;
#pragma unroll
    for (int p = 0; p < 4; p++) {
        int q = tid + p * 128;
        int row = q >> 4, col = (q & 15) * 4;
        uint32_t soff = (uint32_t)(row * B_STRIDE + col) * 4;
        size_t goff = gbase + (size_t)row * ldB + col;
        cp_async16(base_h + soff, GH + goff);
        cp_async16(base_l + soff, GL + goff);
    }
}

// One k8 step: warp (wm,wn) computes its 32x32 with 3xTF32 (2 m-tiles x 4 n-tiles).
__device__ __forceinline__ void mma_k8p(
    const uint32_t* __restrict__ Ah, const uint32_t* __restrict__ Al,
    const uint32_t* __restrict__ Bh, const uint32_t* __restrict__ Bl,
    int wm, int wn, int lane, int k8, float acc[2][4][4]) {
    const int lr = lane >> 2, lc = lane & 3;
    uint32_t ah[2][4], al[2][4];
#pragma unroll
    for (int mt = 0; mt < 2; mt++) {
        int m = wm * 32 + mt * 16 + lr;
        ah[mt][0] = Ah[m * A_STRIDE + k8 + lc];
        ah[mt][1] = Ah[(m + 8) * A_STRIDE + k8 + lc];
        ah[mt][2] = Ah[m * A_STRIDE + k8 + lc + 4];
        ah[mt][3] = Ah[(m + 8) * A_STRIDE + k8 + lc + 4];
        al[mt][0] = Al[m * A_STRIDE + k8 + lc];
        al[mt][1] = Al[(m + 8) * A_STRIDE + k8 + lc];
        al[mt][2] = Al[m * A_STRIDE + k8 + lc + 4];
        al[mt][3] = Al[(m + 8) * A_STRIDE + k8 + lc + 4];
    }
#pragma unroll
    for (int nt = 0; nt < 4; nt++) {
        int n = wn * 32 + nt * 8 + lr;
        uint32_t bh[2], bl[2];
        bh[0] = Bh[(k8 + lc) * B_STRIDE + n];
        bh[1] = Bh[(k8 + lc + 4) * B_STRIDE + n];
        bl[0] = Bl[(k8 + lc) * B_STRIDE + n];
        bl[1] = Bl[(k8 + lc + 4) * B_STRIDE + n];
#pragma unroll
        for (int mt = 0; mt < 2; mt++) {
            MMA(acc[mt][nt], ah[mt], bl);
            MMA(acc[mt][nt], al[mt], bh);
            MMA(acc[mt][nt], ah[mt], bh);
        }
    }
}

// ============ weight pre-split (once per launch; bit-identical to in-kernel split) ====
__global__ void split_sel(const float* __restrict__ src, int sel, int n4) {
    int i = blockIdx.x * blockDim.x + threadIdx.x;
    if (i >= n4) return;
    uint32_t* hi = (sel == 0) ? g_WinH : (sel == 1) ? g_symWH : g_opsWH;
    uint32_t* lo = (sel == 0) ? g_WinL : (sel == 1) ? g_symWL : g_opsWL;
    float4 v = reinterpret_cast<const float4*>(src)[i];
    uint4 h, l; split4(v, h, l);
    reinterpret_cast<uint4*>(hi)[i] = h;
    reinterpret_cast<uint4*>(lo)[i] = l;
}

// ============ GEMM 1 (3xTF32, cp.async B): z = x @ W_in + b_in ============
__global__ __launch_bounds__(128) void gemm_z_tc(
    const float* __restrict__ A, const float* __restrict__ bias) {
    extern __shared__ uint32_t smem[];
    uint32_t* Ah = smem;
    uint32_t* Al = smem + 2304;
    const int tid = threadIdx.x, lane = tid & 31, warp = tid >> 5;
    const int wm = warp & 1, wn = warp >> 1;
    const int bm = blockIdx.x * 64, bn = blockIdx.y * 64;
    const int mrow = tid >> 3, kq = (tid & 7) * 4;
    float acc[2][4][4] = {};
    float4 aReg[4];
#pragma unroll
    for (int i = 0; i < 4; i++)
        aReg[i] = *reinterpret_cast<const float4*>(A + (size_t)(bm + i * 16 + mrow) * INDIM + kq);
    stage_B(0, g_WinH, g_WinL, (size_t)0 * Dm + bn, Dm, tid);
    CP_COMMIT();
    for (int k0 = 0; k0 < INDIM; k0 += 32) {
        const int s = (k0 >> 5) & 1;
        CP_WAIT0();
        __syncthreads();
#pragma unroll
        for (int i = 0; i < 4; i++) {
            uint4 h, l; split4(aReg[i], h, l);
            int m = i * 16 + mrow;
            *reinterpret_cast<uint4*>(&Ah[m * A_STRIDE + kq]) = h;
            *reinterpret_cast<uint4*>(&Al[m * A_STRIDE + kq]) = l;
        }
        if (k0 + 32 < INDIM) {
#pragma unroll
            for (int i = 0; i < 4; i++)
                aReg[i] = *reinterpret_cast<const float4*>(
                    A + (size_t)(bm + i * 16 + mrow) * INDIM + k0 + 32 + kq);
            stage_B(s ^ 1, g_WinH, g_WinL, (size_t)(k0 + 32) * Dm + bn, Dm, tid);
        }
        CP_COMMIT();
        __syncthreads();
        const uint32_t* Bh = smem + 4608 + s * 4608;
        const uint32_t* Bl = Bh + 2304;
        mma_k8p(Ah, Al, Bh, Bl, wm, wn, lane, 0, acc);
        mma_k8p(Ah, Al, Bh, Bl, wm, wn, lane, 8, acc);
        mma_k8p(Ah, Al, Bh, Bl, wm, wn, lane, 16, acc);
        mma_k8p(Ah, Al, Bh, Bl, wm, wn, lane, 24, acc);
    }
    const int lr = lane >> 2, lc = lane & 3;
#pragma unroll
    for (int mt = 0; mt < 2; mt++)
#pragma unroll
        for (int nt = 0; nt < 4; nt++) {
            int m0 = bm + wm * 32 + mt * 16 + lr;
            int n0 = bn + wn * 32 + nt * 8 + 2 * lc;
            float b0 = bias[n0], b1 = bias[n0 + 1];
            g_z[(size_t)m0 * Dm + n0]           = acc[mt][nt][0] + b0;
            g_z[(size_t)m0 * Dm + n0 + 1]       = acc[mt][nt][1] + b1;
            g_z[(size_t)(m0 + 8) * Dm + n0]     = acc[mt][nt][2] + b0;
            g_z[(size_t)(m0 + 8) * Dm + n0 + 1] = acc[mt][nt][3] + b1;
        }
}

// ======= GEMM 2 (3xTF32, cp.async B): sym[b, n*128+s] = sum_d z[b,d]*sym_W[n,d,s] =====
__global__ __launch_bounds__(128) void gemm_sym_tc(float* __restrict__ symOut) {
    extern __shared__ uint32_t smem[];
    uint32_t* Ah = smem;
    uint32_t* Al = smem + 2304;
    const int tid = threadIdx.x, lane = tid & 31, warp = tid >> 5;
    const int wm = warp & 1, wn = warp >> 1;
    const int bm = blockIdx.x * 64, bn = blockIdx.y * 64;
    const int mrow = tid >> 3, kq = (tid & 7) * 4;
    const size_t boff = (size_t)(bn >> 7) * (Dm * Ss) + (bn & 127);
    float acc[2][4][4] = {};
    float4 aReg[4];
#pragma unroll
    for (int i = 0; i < 4; i++)
        aReg[i] = *reinterpret_cast<const float4*>(g_z + (size_t)(bm + i * 16 + mrow) * Dm + kq);
    stage_B(0, g_symWH, g_symWL, boff, Ss, tid);
    CP_COMMIT();
    for (int k0 = 0; k0 < Dm; k0 += 32) {
        const int s = (k0 >> 5) & 1;
        CP_WAIT0();
        __syncthreads();
#pragma unroll
        for (int i = 0; i < 4; i++) {
            uint4 h, l; split4(aReg[i], h, l);
            int m = i * 16 + mrow;
            *reinterpret_cast<uint4*>(&Ah[m * A_STRIDE + kq]) = h;
            *reinterpret_cast<uint4*>(&Al[m * A_STRIDE + kq]) = l;
        }
        if (k0 + 32 < Dm) {
#pragma unroll
            for (int i = 0; i < 4; i++)
                aReg[i] = *reinterpret_cast<const float4*>(
                    g_z + (size_t)(bm + i * 16 + mrow) * Dm + k0 + 32 + kq);
            stage_B(s ^ 1, g_symWH, g_symWL, boff + (size_t)(k0 + 32) * Ss, Ss, tid);
        }
        CP_COMMIT();
        __syncthreads();
        const uint32_t* Bh = smem + 4608 + s * 4608;
        const uint32_t* Bl = Bh + 2304;
        mma_k8p(Ah, Al, Bh, Bl, wm, wn, lane, 0, acc);
        mma_k8p(Ah, Al, Bh, Bl, wm, wn, lane, 8, acc);
        mma_k8p(Ah, Al, Bh, Bl, wm, wn, lane, 16, acc);
        mma_k8p(Ah, Al, Bh, Bl, wm, wn, lane, 24, acc);
    }
    const int lr = lane >> 2, lc = lane & 3;
#pragma unroll
    for (int mt = 0; mt < 2; mt++)
#pragma unroll
        for (int nt = 0; nt < 4; nt++) {
            int m0 = bm + wm * 32 + mt * 16 + lr;
            int n0 = bn + wn * 32 + nt * 8 + 2 * lc;
            symOut[(size_t)m0 * (Nn * Ss) + n0]           = acc[mt][nt][0];
            symOut[(size_t)m0 * (Nn * Ss) + n0 + 1]       = acc[mt][nt][1];
            symOut[(size_t)(m0 + 8) * (Nn * Ss) + n0]     = acc[mt][nt][2];
            symOut[(size_t)(m0 + 8) * (Nn * Ss) + n0 + 1] = acc[mt][nt][3];
        }
}

// ================== symmean[b,s] = mean_n sym[b,n,s] ==================
__global__ void mean_kernel(const float* __restrict__ symOut) {
    int i = blockIdx.x * blockDim.x + threadIdx.x;
    int b = i >> 7, s = i & 127;
    const float* p = symOut + (size_t)b * (Nn * Ss) + s;
    float sum = 0.f;
#pragma unroll
    for (int n = 0; n < Nn; n++) sum += p[n * Ss];
    g_symmean[i] = sum * 0.125f;
}

// ====== router: compensated-fp32 logits + argmax -> prog (frozen since R3) ======
__global__ __launch_bounds__(288) void router_kernel(
    const float* __restrict__ RW, const float* __restrict__ rb, float* __restrict__ progf) {
    __shared__ float rin[8][644];
    __shared__ float lg[8][36];
    const int b0 = blockIdx.x * 8;
    const int tid = threadIdx.x;
    for (int i = tid; i < 8 * 640; i += 288) {
        int t = i / 640, k = i - t * 640;
        rin[t][k] = (k < Dm) ? g_z[(size_t)(b0 + t) * Dm + k]
                             : g_symmean[(size_t)(b0 + t) * Ss + (k - Dm)];
    }
    __syncthreads();
    {
        const int t = tid / 36, j = tid - t * 36;
        const float* rw = RW + j;
        float s[4] = {0.f, 0.f, 0.f, 0.f};
        float c[4] = {0.f, 0.f, 0.f, 0.f};
#pragma unroll 2
        for (int k = 0; k < 640; k += 4) {
#pragma unroll
            for (int i = 0; i < 4; i++) {
                float x = rin[t][k + i];
                float w = __ldg(&rw[(k + i) * 36]);
                float p = __fmul_rn(x, w);
                float e = __fmaf_rn(x, w, -p);
                float t1  = __fadd_rn(s[i], p);
                float bb  = __fsub_rn(t1, s[i]);
                float er1 = __fadd_rn(__fsub_rn(s[i], __fsub_rn(t1, bb)),
                                      __fsub_rn(p, bb));
                s[i] = t1;
                c[i] = __fadd_rn(c[i], __fadd_rn(er1, e));
            }
        }
        float S = rb[j], C = 0.f;
#pragma unroll
        for (int i = 0; i < 4; i++) {
            float t1  = __fadd_rn(S, s[i]);
            float bb  = __fsub_rn(t1, S);
            float er1 = __fadd_rn(__fsub_rn(S, __fsub_rn(t1, bb)),
                                  __fsub_rn(s[i], bb));
            S = t1;
            C = __fadd_rn(C, __fadd_rn(er1, c[i]));
        }
        lg[t][j] = __fadd_rn(S, C);
    }
    __syncthreads();
    if (tid < 32) {
        int t = tid >> 2, h = tid & 3;
        const float* l = &lg[t][h * 9];
        float best = l[0]; int bi = 0;
#pragma unroll
        for (int j = 1; j < 9; j++)
            if (l[j] > best) { best = l[j]; bi = j; }
        g_prog[(b0 + t) * HOPS + h] = bi;
        progf[(b0 + t) * HOPS + h] = (float)bi;
    }
}

// ======= schedule: group active tokens by (hop, expert); build 64-row tiles =======
__global__ void schedule_kernel() {
    __shared__ int cnt[HOPS][Nn];
    __shared__ int cur[HOPS][Nn];
    const int tid = threadIdx.x;
    if (tid < HOPS * Nn) cnt[tid / Nn][tid % Nn] = 0;
    __syncthreads();
    for (int b = tid; b < Bsz; b += blockDim.x) {
        bool act = true;
        for (int t = 0; t < HOPS; t++) {
            int e = g_prog[b * HOPS + t];
            act = act && (e != Nn);
            if (act) atomicAdd(&cnt[t][e], 1);
        }
    }
    __syncthreads();
    if (tid < HOPS) {
        int t = tid, p = 0, nt = 0;
        for (int e = 0; e < Nn; e++) {
            cur[t][e] = p;
            int c = cnt[t][e], q = p;
            while (c > 0) {
                g_tileE[t][nt] = e; g_tileS[t][nt] = q;
                g_tileC[t][nt] = (c < 64) ? c : 64;
                q += 64; c -= 64; nt++;
            }
            p += cnt[t][e];
        }
        g_numTiles[t] = nt;
    }
    __syncthreads();
    for (int b = tid; b < Bsz; b += blockDim.x) {
        bool act = true;
        for (int t = 0; t < HOPS; t++) {
            int e = g_prog[b * HOPS + t];
            act = act && (e != Nn);
            if (act) { int p = atomicAdd(&cur[t][e], 1); g_order[t][p] = b; }
        }
    }
}

// == hop (3xTF32, cp.async B): dst[tok] = gelu(src[tok] @ ops_W[e] + ops_b[e]) ==
// No inter-hop copies: active(h+1) ⊆ active(h), so hop h+1 only reads rows hop h wrote.
__global__ __launch_bounds__(128) void hop_tc(
    int hop, int srcSel, const float* __restrict__ opsB) {
    if ((int)blockIdx.x >= g_numTiles[hop]) return;
    extern __shared__ uint32_t smem[];
    __shared__ int toks[64];
    uint32_t* Ah = smem;
    uint32_t* Al = smem + 2304;
    const float* src = (srcSel == 0) ? g_z : g_buf;
    float* dst = (srcSel == 0) ? g_buf : g_z;
    const int e     = g_tileE[hop][blockIdx.x];
    const int start = g_tileS[hop][blockIdx.x];
    const int cnt   = g_tileC[hop][blockIdx.x];
    const int bn    = blockIdx.y * 64;
    const int tid = threadIdx.x, lane = tid & 31, warp = tid >> 5;
    const int wm = warp & 1, wn = warp >> 1;
    const int mrow = tid >> 3, kq = (tid & 7) * 4;
    if (tid < 64) toks[tid] = (tid < cnt) ? g_order[hop][start + tid] : -1;
    const uint32_t* WH = g_opsWH + (size_t)e * (Dm * Dm);
    const uint32_t* WL = g_opsWL + (size_t)e * (Dm * Dm);
    stage_B(0, WH, WL, (size_t)0 * Dm + bn, Dm, tid);
    CP_COMMIT();
    __syncthreads();   // toks visible
    int myTok[4];
#pragma unroll
    for (int i = 0; i < 4; i++) myTok[i] = toks[i * 16 + mrow];
    float acc[2][4][4] = {};
    float4 aReg[4];
#pragma unroll
    for (int i = 0; i < 4; i++) {
        aReg[i] = make_float4(0.f, 0.f, 0.f, 0.f);
        if (myTok[i] >= 0)
            aReg[i] = *reinterpret_cast<const float4*>(src + (size_t)myTok[i] * Dm + kq);
    }
    for (int k0 = 0; k0 < Dm; k0 += 32) {
        const int s = (k0 >> 5) & 1;
        CP_WAIT0();
        __syncthreads();
#pragma unroll
        for (int i = 0; i < 4; i++) {
            uint4 h, l; split4(aReg[i], h, l);
            int m = i * 16 + mrow;
            *reinterpret_cast<uint4*>(&Ah[m * A_STRIDE + kq]) = h;
            *reinterpret_cast<uint4*>(&Al[m * A_STRIDE + kq]) = l;
        }
        if (k0 + 32 < Dm) {
#pragma unroll
            for (int i = 0; i < 4; i++)
                if (myTok[i] >= 0)
                    aReg[i] = *reinterpret_cast<const float4*>(
                        src + (size_t)myTok[i] * Dm + k0 + 32 + kq);
            stage_B(s ^ 1, WH, WL, (size_t)(k0 + 32) * Dm + bn, Dm, tid);
        }
        CP_COMMIT();
        __syncthreads();
        const uint32_t* Bh = smem + 4608 + s * 4608;
        const uint32_t* Bl = Bh + 2304;
        mma_k8p(Ah, Al, Bh, Bl, wm, wn, lane, 0, acc);
        mma_k8p(Ah, Al, Bh, Bl, wm, wn, lane, 8, acc);
        mma_k8p(Ah, Al, Bh, Bl, wm, wn, lane, 16, acc);
        mma_k8p(Ah, Al, Bh, Bl, wm, wn, lane, 24, acc);
    }
    const int lr = lane >> 2, lc = lane & 3;
#pragma unroll
    for (int mt = 0; mt < 2; mt++) {
        int r0 = wm * 32 + mt * 16 + lr;
        int tk0 = toks[r0], tk1 = toks[r0 + 8];
#pragma unroll
        for (int nt = 0; nt < 4; nt++) {
            int n0 = bn + wn * 32 + nt * 8 + 2 * lc;
            float b0 = opsB[e * Dm + n0], b1 = opsB[e * Dm + n0 + 1];
            if (tk0 >= 0) {
                dst[(size_t)tk0 * Dm + n0]     = gelu_tanh(acc[mt][nt][0] + b0);
                dst[(size_t)tk0 * Dm + n0 + 1] = gelu_tanh(acc[mt][nt][1] + b1);
            }
            if (tk1 >= 0) {
                dst[(size_t)tk1 * Dm + n0]     = gelu_tanh(acc[mt][nt][2] + b0);
                dst[(size_t)tk1 * Dm + n0 + 1] = gelu_tanh(acc[mt][nt][3] + b1);
            }
        }
    }
}

// ===== final gather: out[b] = buffer holding b's value after its last active hop =====
__global__ void gather_out(float* __restrict__ out) {
    int idx = blockIdx.x * blockDim.x + threadIdx.x;   // over Bsz*Dm/4 float4s
    int b = idx >> 7;
    int nact = 0;
#pragma unroll
    for (int t = 0; t < HOPS; t++) {
        if (g_prog[b * HOPS + t] == Nn) break;
        nact++;
    }
    const float* src = (nact & 1) ? g_buf : g_z;
    reinterpret_cast<float4*>(out)[idx] = reinterpret_cast<const float4*>(src)[idx];
}

// =========================== launch ===========================
extern "C" void kernel_launch(void* const* d_in, const int* in_sizes, int n_in,
                              void* d_out, int out_size) {
    const float* x        = (const float*)d_in[0];
    const float* W_in     = (const float*)d_in[1];
    const float* b_in     = (const float*)d_in[2];
    const float* ops_W    = (const float*)d_in[3];
    const float* ops_b    = (const float*)d_in[4];
    const float* sym_W    = (const float*)d_in[5];
    const float* router_W = (const float*)d_in[6];
    const float* router_b = (const float*)d_in[7];
    (void)in_sizes; (void)n_in; (void)out_size;

    float* out   = (float*)d_out;                 // [B, D]
    float* progf = out + Bsz * Dm;                // [B, HOPS] as float
    float* sym   = progf + Bsz * HOPS;            // [B, N, S]

    // opt in to 54KB dynamic smem (idempotent; host-side, not a stream op)
    cudaFuncSetAttribute(gemm_z_tc,  cudaFuncAttributeMaxDynamicSharedMemorySize, SMEM_BYTES);
    cudaFuncSetAttribute(gemm_sym_tc, cudaFuncAttributeMaxDynamicSharedMemorySize, SMEM_BYTES);
    cudaFuncSetAttribute(hop_tc,     cudaFuncAttributeMaxDynamicSharedMemorySize, SMEM_BYTES);

    // pre-split weights into tf32 hi/lo
    split_sel<<<(INDIM * Dm / 4 + 255) / 256, 256>>>(W_in, 0, INDIM * Dm / 4);
    split_sel<<<(Nn * Dm * Ss / 4 + 255) / 256, 256>>>(sym_W, 1, Nn * Dm * Ss / 4);
    split_sel<<<(Nn * Dm * Dm / 4 + 255) / 256, 256>>>(ops_W, 2, Nn * Dm * Dm / 4);

    gemm_z_tc   <<<dim3(Bsz / 64, Dm / 64), 128, SMEM_BYTES>>>(x, b_in);
    gemm_sym_tc <<<dim3(Bsz / 64, (Nn * Ss) / 64), 128, SMEM_BYTES>>>(sym);
    mean_kernel <<<(Bsz * Ss) / 256, 256>>>(sym);
    router_kernel<<<Bsz / 8, 288>>>(router_W, router_b, progf);
    schedule_kernel<<<1, 512>>>();

    hop_tc<<<dim3(MAXT, Dm / 64), 128, SMEM_BYTES>>>(0, 0, ops_b);  // z   -> buf
    hop_tc<<<dim3(MAXT, Dm / 64), 128, SMEM_BYTES>>>(1, 1, ops_b);  // buf -> z
    hop_tc<<<dim3(MAXT, Dm / 64), 128, SMEM_BYTES>>>(2, 0, ops_b);  // z   -> buf
    hop_tc<<<dim3(MAXT, Dm / 64), 128, SMEM_BYTES>>>(3, 1, ops_b);  // buf -> z

    gather_out<<<(Bsz * Dm / 4) / 256, 256>>>(out);
}